// round 14
// baseline (speedup 1.0000x reference)
#include <cuda_runtime.h>
#include <cuda_bf16.h>
#include <stdint.h>

#define SEQ 80
#define EMB 100
#define VOCAB 10000
#define BMAX 16384
#define WSTRIDE 72   // padded bf16 row stride: conflict-free ldmatrix (verified)

// Precomputed emb @ Wx0 + b0 in BF16, columns permuted: col j -> slot sidx_full(j)
__device__ uint16_t g_embW0bf[VOCAB * 64];
// Transposed tokens [SEQ][B]
__device__ int g_tokT[SEQ * BMAX];
// Pre-swizzled bf16 weight image (exact smem layout): Wh0^T, Wx1^T, Wh1^T
__device__ uint16_t g_wsm[3 * 64 * WSTRIDE];

#define EMBW_BLOCKS 313

// storage slot of unit j: thread tq's 16 values land contiguous (verified R10)
__host__ __device__ __forceinline__ int sidx_full(int j) {
    int nt = j >> 3, tq = (j >> 1) & 3, e = j & 1;
    return 16 * tq + 2 * nt + e;
}

// ---------------------------------------------------------------------------
// Prep (fused): embW0 (bf16, permuted cols) | weight image | token transpose
// ---------------------------------------------------------------------------
__global__ void __launch_bounds__(256) prep_kernel(const float* __restrict__ emb,
                                                   const float* __restrict__ Wx0,
                                                   const float* __restrict__ b0,
                                                   const float* __restrict__ Wh0,
                                                   const float* __restrict__ Wx1,
                                                   const float* __restrict__ Wh1,
                                                   const int*   __restrict__ tokens,
                                                   int B) {
    int tid = threadIdx.x;
    if (blockIdx.x < EMBW_BLOCKS) {
        __shared__ float sW[EMB * 64];
        __shared__ float sE[32 * EMB];
        for (int i = tid; i < EMB * 64; i += 256) sW[i] = Wx0[i];
        int vbase = blockIdx.x * 32;
        for (int i = tid; i < 32 * EMB; i += 256) {
            int r = vbase + i / EMB;
            sE[i] = emb[(r < VOCAB ? r : 0) * EMB + i % EMB];
        }
        __syncthreads();

        int tcol = tid & 15;
        int trow = tid >> 4;
        float a0[4], a1[4];
        *reinterpret_cast<float4*>(a0) = *reinterpret_cast<const float4*>(b0 + tcol * 4);
        *reinterpret_cast<float4*>(a1) = *reinterpret_cast<float4*>(a0);
        const float* e0 = sE + trow * EMB;
        const float* e1 = sE + (trow + 16) * EMB;
        const float4* sW4 = reinterpret_cast<const float4*>(sW);
        #pragma unroll 10
        for (int k = 0; k < EMB; ++k) {
            float4 w = sW4[k * 16 + tcol];
            float ev0 = e0[k], ev1 = e1[k];
            a0[0] += ev0 * w.x; a0[1] += ev0 * w.y; a0[2] += ev0 * w.z; a0[3] += ev0 * w.w;
            a1[0] += ev1 * w.x; a1[1] += ev1 * w.y; a1[2] += ev1 * w.z; a1[3] += ev1 * w.w;
        }
        int v0 = vbase + trow, v1 = vbase + trow + 16;
        #pragma unroll
        for (int jj = 0; jj < 4; ++jj) {
            int s = sidx_full(tcol * 4 + jj);
            __nv_bfloat16 q0 = __float2bfloat16(a0[jj]);
            __nv_bfloat16 q1 = __float2bfloat16(a1[jj]);
            if (v0 < VOCAB) g_embW0bf[v0 * 64 + s] = *reinterpret_cast<uint16_t*>(&q0);
            if (v1 < VOCAB) g_embW0bf[v1 * 64 + s] = *reinterpret_cast<uint16_t*>(&q1);
        }
        return;
    }
    if (blockIdx.x == EMBW_BLOCKS) {
        const float* Ws[3] = {Wh0, Wx1, Wh1};
        for (int i = tid; i < 3 * 64 * 64; i += 256) {
            int w = i >> 12, r = i & 4095;
            int k = r >> 6, n = r & 63;
            __nv_bfloat16 v = __float2bfloat16(Ws[w][r]);
            g_wsm[w * 64 * WSTRIDE + n * WSTRIDE + k] = *reinterpret_cast<uint16_t*>(&v);
        }
        return;
    }
    int b = (blockIdx.x - EMBW_BLOCKS - 1) * 256 + tid;
    if (b < B) {
        #pragma unroll
        for (int s = 0; s < SEQ; ++s)
            g_tokT[s * B + b] = tokens[b * SEQ + s];
    }
}

// ---------------------------------------------------------------------------
// PTX helpers (verified)
// ---------------------------------------------------------------------------
__device__ __forceinline__ void mma16816(float& d0, float& d1, float& d2, float& d3,
                                         uint32_t a0, uint32_t a1, uint32_t a2, uint32_t a3,
                                         uint32_t b0, uint32_t b1) {
    asm("mma.sync.aligned.m16n8k16.row.col.f32.bf16.bf16.f32 "
        "{%0,%1,%2,%3},{%4,%5,%6,%7},{%8,%9},{%0,%1,%2,%3};"
        : "+f"(d0), "+f"(d1), "+f"(d2), "+f"(d3)
        : "r"(a0), "r"(a1), "r"(a2), "r"(a3), "r"(b0), "r"(b1));
}

__device__ __forceinline__ void ldsm4(uint32_t& x, uint32_t& y, uint32_t& z, uint32_t& w,
                                      uint32_t saddr) {
    asm volatile("ldmatrix.sync.aligned.m8n8.x4.shared.b16 {%0,%1,%2,%3}, [%4];"
                 : "=r"(x), "=r"(y), "=r"(z), "=r"(w) : "r"(saddr));
}

__device__ __forceinline__ uint32_t packbf(float lo, float hi) {
    uint32_t r;
    asm("cvt.rn.bf16x2.f32 %0, %1, %2;" : "=r"(r) : "f"(hi), "f"(lo));
    return r;
}

__device__ __forceinline__ uint32_t tanh_bf16x2(uint32_t v) {
    uint32_t r;
    asm("tanh.approx.bf16x2 %0, %1;" : "=r"(r) : "r"(v));
    return r;
}

__device__ __forceinline__ float fast_tanh(float x) {
    float y;
    asm("tanh.approx.f32 %0, %1;" : "=f"(y) : "f"(x));
    return y;
}

// bf16x2 word -> two fp32 (lo = low half, hi = high half); pure ALU
__device__ __forceinline__ void bf2f(uint32_t u, float& lo, float& hi) {
    lo = __uint_as_float(u << 16);
    hi = __uint_as_float(u & 0xFFFF0000u);
}

// acc[32] -> h[16] A-frag words (verified mapping), tanh applied
__device__ __forceinline__ void tanh_frags(const float* acc, uint32_t* h) {
    #pragma unroll
    for (int k = 0; k < 4; ++k) {
        h[k*4+0] = tanh_bf16x2(packbf(acc[4*k],      acc[4*k+1]));
        h[k*4+1] = tanh_bf16x2(packbf(acc[16+4*k],   acc[16+4*k+1]));
        h[k*4+2] = tanh_bf16x2(packbf(acc[4*k+2],    acc[4*k+3]));
        h[k*4+3] = tanh_bf16x2(packbf(acc[16+4*k+2], acc[16+4*k+3]));
    }
}

// ---------------------------------------------------------------------------
// Kernel 2: bf16 recurrence, ONE warp per CTA. Wh0 fully hoisted (64 words),
// Wh1 hoisted kp=0 fully + kp=1 nt<4 (48 words). bf16 gather table: raw
// uint32x2 prefetch (16 regs), converted at loop top. Per-step smem:
// Wx1 16 ldsm + Wh1 4 ldsm. grid = B/16 = 1024.
// ---------------------------------------------------------------------------
__global__ void __launch_bounds__(32, 7) rnn_kernel(
    const float* __restrict__ b1,
    const float* __restrict__ Wout,
    const float* __restrict__ bout,
    float*       __restrict__ out,
    int B) {
    __shared__ __align__(16) uint16_t sW[3 * 64 * WSTRIDE];
    __shared__ float sB1[64];

    // preamble: copy pre-swizzled weight image; stage b1 permuted
    {
        const uint4* src = reinterpret_cast<const uint4*>(g_wsm);
        uint4* dst = reinterpret_cast<uint4*>(sW);
        #pragma unroll 6
        for (int i = threadIdx.x; i < 3 * 64 * WSTRIDE / 8; i += 32) dst[i] = src[i];
    }
    #pragma unroll
    for (int idx = threadIdx.x; idx < 64; idx += 32) {
        int tq_ = idx >> 4, r = idx & 15;
        int nt = r >> 1, e = r & 1;
        sB1[idx] = b1[8 * nt + 2 * tq_ + e];
    }
    __syncwarp();

    const int lane = threadIdx.x;
    const int g  = lane >> 2;
    const int tq = lane & 3;
    const int base = blockIdx.x * 16;

    int rc[2];
    #pragma unroll
    for (int i = 0; i < 2; ++i) {
        int r = base + g + 8 * i;
        rc[i] = r < B ? r : (B - 1);
    }

    // ldmatrix addressing (verified)
    const int laneoff = (lane & 7) * WSTRIDE + (lane >> 3) * 8;
    uint32_t swb = (uint32_t)__cvta_generic_to_shared(sW);
    const uint32_t aW0 = swb + 2 * laneoff;                    // Wh0
    const uint32_t aW1 = aW0 + 2 * (64 * WSTRIDE);             // Wx1
    const uint32_t aW2 = aW1 + 2 * (64 * WSTRIDE);             // Wh1

    // ---- hoist Wh0 fully (64) + Wh1 kp=0 (32) + Wh1 kp=1 nt<4 (16) ----
    uint32_t wf0[64];   // [(kp*8+nt)*4 + q]
    uint32_t wf2[48];   // kp=0: [nt*4+q] ; kp=1 nt<4: [32 + nt*4 + q]
    #pragma unroll
    for (int kp = 0; kp < 2; ++kp) {
        #pragma unroll
        for (int nt = 0; nt < 8; ++nt) {
            uint32_t off = 2 * (uint32_t)(nt * 8 * WSTRIDE + kp * 32);
            int bi = (kp * 8 + nt) * 4;
            ldsm4(wf0[bi + 0], wf0[bi + 1], wf0[bi + 2], wf0[bi + 3], aW0 + off);
        }
    }
    #pragma unroll
    for (int nt = 0; nt < 8; ++nt) {
        uint32_t off = 2 * (uint32_t)(nt * 8 * WSTRIDE);
        ldsm4(wf2[nt*4 + 0], wf2[nt*4 + 1], wf2[nt*4 + 2], wf2[nt*4 + 3], aW2 + off);
    }
    #pragma unroll
    for (int nt = 0; nt < 4; ++nt) {
        uint32_t off = 2 * (uint32_t)(nt * 8 * WSTRIDE + 32);
        ldsm4(wf2[32 + nt*4 + 0], wf2[32 + nt*4 + 1],
              wf2[32 + nt*4 + 2], wf2[32 + nt*4 + 3], aW2 + off);
    }

    uint32_t h0f[16], h1f[16];     // A-frags [k(4)][q(4)]
    #pragma unroll
    for (int i = 0; i < 16; ++i) { h0f[i] = 0u; h1f[i] = 0u; }

    // raw bf16 gather buffer: [i(2)][w(8)] uint32 = 16 regs
    uint32_t gx[16];
    #pragma unroll
    for (int i = 0; i < 2; ++i) {
        int tok = g_tokT[rc[i]];
        const uint4* rowp = reinterpret_cast<const uint4*>(g_embW0bf + tok * 64 + tq * 16);
        uint4 v0 = rowp[0], v1 = rowp[1];
        gx[i*8+0]=v0.x; gx[i*8+1]=v0.y; gx[i*8+2]=v0.z; gx[i*8+3]=v0.w;
        gx[i*8+4]=v1.x; gx[i*8+5]=v1.y; gx[i*8+6]=v1.z; gx[i*8+7]=v1.w;
    }

    const float4* bp = reinterpret_cast<const float4*>(sB1 + tq * 16);
    float accB[32];

    #pragma unroll 1
    for (int ts = 0; ts < SEQ; ++ts) {
        int tsn = (ts + 1 < SEQ) ? ts + 1 : SEQ - 1;
        int tkn[2];
        #pragma unroll
        for (int i = 0; i < 2; ++i) tkn[i] = g_tokT[tsn * B + rc[i]];

        // convert raw bf16 gather -> accA (pure ALU, 32 ops)
        float accA[32];
        #pragma unroll
        for (int i = 0; i < 2; ++i)
            #pragma unroll
            for (int w = 0; w < 8; ++w)
                bf2f(gx[i*8 + w], accA[i*16 + 2*w], accA[i*16 + 2*w + 1]);

        // accB = b1 (4 broadcast LDS.128)
        #pragma unroll
        for (int f = 0; f < 4; ++f) {
            float4 bv = bp[f];
            accB[f*4+0] = bv.x; accB[f*4+1] = bv.y;
            accB[f*4+2] = bv.z; accB[f*4+3] = bv.w;
            accB[16+f*4+0] = bv.x; accB[16+f*4+1] = bv.y;
            accB[16+f*4+2] = bv.z; accB[16+f*4+3] = bv.w;
        }

        // recurrent GEMM pair: accA += h0 @ Wh0 (regs) ; accB += h1 @ Wh1
        // (kp=0 + kp=1 nt<4 from regs; kp=1 nt>=4 via 4 inline ldsm)
        #pragma unroll
        for (int kp = 0; kp < 2; ++kp) {
            #pragma unroll
            for (int nt = 0; nt < 8; ++nt) {
                int bi = (kp * 8 + nt) * 4;
                int k0 = 2 * kp;
                uint32_t bx, by, bz, bw;
                if (kp == 0) {
                    bx = wf2[nt*4 + 0]; by = wf2[nt*4 + 1];
                    bz = wf2[nt*4 + 2]; bw = wf2[nt*4 + 3];
                } else if (nt < 4) {
                    bx = wf2[32 + nt*4 + 0]; by = wf2[32 + nt*4 + 1];
                    bz = wf2[32 + nt*4 + 2]; bw = wf2[32 + nt*4 + 3];
                } else {
                    uint32_t off = 2 * (uint32_t)(nt * 8 * WSTRIDE + 32);
                    ldsm4(bx, by, bz, bw, aW2 + off);
                }
                mma16816(accA[nt*2], accA[nt*2+1], accA[16+nt*2], accA[16+nt*2+1],
                         h0f[k0*4+0], h0f[k0*4+1], h0f[k0*4+2], h0f[k0*4+3],
                         wf0[bi + 0], wf0[bi + 1]);
                mma16816(accB[nt*2], accB[nt*2+1], accB[16+nt*2], accB[16+nt*2+1],
                         h1f[k0*4+0], h1f[k0*4+1], h1f[k0*4+2], h1f[k0*4+3],
                         bx, by);
                mma16816(accA[nt*2], accA[nt*2+1], accA[16+nt*2], accA[16+nt*2+1],
                         h0f[(k0+1)*4+0], h0f[(k0+1)*4+1], h0f[(k0+1)*4+2], h0f[(k0+1)*4+3],
                         wf0[bi + 2], wf0[bi + 3]);
                mma16816(accB[nt*2], accB[nt*2+1], accB[16+nt*2], accB[16+nt*2+1],
                         h1f[(k0+1)*4+0], h1f[(k0+1)*4+1], h1f[(k0+1)*4+2], h1f[(k0+1)*4+3],
                         bz, bw);
            }
        }

        // h0 = tanh(accA) -> A-frags (accA dead after this)
        tanh_frags(accA, h0f);

        // prefetch next-step raw gather (4 LDG.128, covers L2 over layer 1)
        #pragma unroll
        for (int i = 0; i < 2; ++i) {
            const uint4* rowp =
                reinterpret_cast<const uint4*>(g_embW0bf + tkn[i] * 64 + tq * 16);
            uint4 v0 = rowp[0], v1 = rowp[1];
            gx[i*8+0]=v0.x; gx[i*8+1]=v0.y; gx[i*8+2]=v0.z; gx[i*8+3]=v0.w;
            gx[i*8+4]=v1.x; gx[i*8+5]=v1.y; gx[i*8+6]=v1.z; gx[i*8+7]=v1.w;
        }

        // accB += h0new @ Wx1 (16 ldsm.x4)
        #pragma unroll
        for (int kp = 0; kp < 2; ++kp) {
            #pragma unroll
            for (int nt = 0; nt < 8; ++nt) {
                uint32_t off = 2 * (uint32_t)(nt * 8 * WSTRIDE + kp * 32);
                uint32_t x1, y1, z1, w1;
                ldsm4(x1, y1, z1, w1, aW1 + off);
                int k0 = 2 * kp;
                mma16816(accB[nt*2], accB[nt*2+1], accB[16+nt*2], accB[16+nt*2+1],
                         h0f[k0*4+0], h0f[k0*4+1], h0f[k0*4+2], h0f[k0*4+3], x1, y1);
                mma16816(accB[nt*2], accB[nt*2+1], accB[16+nt*2], accB[16+nt*2+1],
                         h0f[(k0+1)*4+0], h0f[(k0+1)*4+1], h0f[(k0+1)*4+2], h0f[(k0+1)*4+3],
                         z1, w1);
            }
        }

        // h1 = tanh(accB) -> A-frags
        tanh_frags(accB, h1f);
    }

    // ---- head: sigmoid(tanh(accB) @ Wout + bout), fp32 tanh on final step ----
    float wo[16];
    #pragma unroll
    for (int nt = 0; nt < 8; ++nt) {
        float2 v = *reinterpret_cast<const float2*>(Wout + nt * 8 + tq * 2);
        wo[nt * 2] = v.x; wo[nt * 2 + 1] = v.y;
    }
    float bo = bout[0];
    #pragma unroll
    for (int i = 0; i < 2; ++i) {
        float s = 0.f;
        #pragma unroll
        for (int nt = 0; nt < 8; ++nt) {
            s += fast_tanh(accB[i * 16 + nt * 2])     * wo[nt * 2];
            s += fast_tanh(accB[i * 16 + nt * 2 + 1]) * wo[nt * 2 + 1];
        }
        s += __shfl_xor_sync(0xffffffffu, s, 1);
        s += __shfl_xor_sync(0xffffffffu, s, 2);
        int r = base + g + 8 * i;
        if (tq == 0 && r < B)
            out[r] = 1.0f / (1.0f + __expf(-(s + bo)));
    }
}

// ---------------------------------------------------------------------------
extern "C" void kernel_launch(void* const* d_in, const int* in_sizes, int n_in,
                              void* d_out, int out_size) {
    const int*   tokens = (const int*)  d_in[0];
    const float* emb    = (const float*)d_in[1];
    const float* Wx0    = (const float*)d_in[2];
    const float* Wh0    = (const float*)d_in[3];
    const float* b0     = (const float*)d_in[4];
    const float* Wx1    = (const float*)d_in[5];
    const float* Wh1    = (const float*)d_in[6];
    const float* b1     = (const float*)d_in[7];
    const float* Wout   = (const float*)d_in[8];
    const float* bout   = (const float*)d_in[9];
    float* out = (float*)d_out;

    int B = in_sizes[0] / SEQ;
    if (B > BMAX) B = BMAX;

    int prep_blocks = EMBW_BLOCKS + 1 + (B + 255) / 256;
    prep_kernel<<<prep_blocks, 256>>>(emb, Wx0, b0, Wh0, Wx1, Wh1, tokens, B);

    int nblocks = (B + 15) / 16;
    rnn_kernel<<<nblocks, 32>>>(b1, Wout, bout, out, B);
}

// round 15
// speedup vs baseline: 1.0338x; 1.0338x over previous
#include <cuda_runtime.h>
#include <cuda_bf16.h>
#include <stdint.h>

#define SEQ 80
#define EMB 100
#define VOCAB 10000
#define BMAX 16384
#define WSTRIDE 72   // padded bf16 row stride: conflict-free ldmatrix (verified)

// Precomputed emb @ Wx0 + b0 (fp32), columns permuted: col j -> slot sidx_full(j)
__device__ float g_embW0[VOCAB * 64];
// Transposed tokens [SEQ][B]
__device__ int g_tokT[SEQ * BMAX];
// Pre-swizzled bf16 weight image (exact smem layout): Wh0^T, Wx1^T, Wh1^T
__device__ uint16_t g_wsm[3 * 64 * WSTRIDE];

#define EMBW_BLOCKS 313

// storage slot of unit j: thread tq's 16 values land contiguous (verified R10)
__host__ __device__ __forceinline__ int sidx_full(int j) {
    int nt = j >> 3, tq = (j >> 1) & 3, e = j & 1;
    return 16 * tq + 2 * nt + e;
}

// ---------------------------------------------------------------------------
// Prep (fused): embW0 (fp32, permuted cols) | weight image | token transpose
// (identical to R13 — verified)
// ---------------------------------------------------------------------------
__global__ void __launch_bounds__(256) prep_kernel(const float* __restrict__ emb,
                                                   const float* __restrict__ Wx0,
                                                   const float* __restrict__ b0,
                                                   const float* __restrict__ Wh0,
                                                   const float* __restrict__ Wx1,
                                                   const float* __restrict__ Wh1,
                                                   const int*   __restrict__ tokens,
                                                   int B) {
    int tid = threadIdx.x;
    if (blockIdx.x < EMBW_BLOCKS) {
        __shared__ float sW[EMB * 64];
        __shared__ float sE[32 * EMB];
        for (int i = tid; i < EMB * 64; i += 256) sW[i] = Wx0[i];
        int vbase = blockIdx.x * 32;
        for (int i = tid; i < 32 * EMB; i += 256) {
            int r = vbase + i / EMB;
            sE[i] = emb[(r < VOCAB ? r : 0) * EMB + i % EMB];
        }
        __syncthreads();

        int tcol = tid & 15;
        int trow = tid >> 4;
        float a0[4], a1[4];
        *reinterpret_cast<float4*>(a0) = *reinterpret_cast<const float4*>(b0 + tcol * 4);
        *reinterpret_cast<float4*>(a1) = *reinterpret_cast<float4*>(a0);
        const float* e0 = sE + trow * EMB;
        const float* e1 = sE + (trow + 16) * EMB;
        const float4* sW4 = reinterpret_cast<const float4*>(sW);
        #pragma unroll 10
        for (int k = 0; k < EMB; ++k) {
            float4 w = sW4[k * 16 + tcol];
            float ev0 = e0[k], ev1 = e1[k];
            a0[0] += ev0 * w.x; a0[1] += ev0 * w.y; a0[2] += ev0 * w.z; a0[3] += ev0 * w.w;
            a1[0] += ev1 * w.x; a1[1] += ev1 * w.y; a1[2] += ev1 * w.z; a1[3] += ev1 * w.w;
        }
        int v0 = vbase + trow, v1 = vbase + trow + 16;
        #pragma unroll
        for (int jj = 0; jj < 4; ++jj) {
            int s = sidx_full(tcol * 4 + jj);
            if (v0 < VOCAB) g_embW0[v0 * 64 + s] = a0[jj];
            if (v1 < VOCAB) g_embW0[v1 * 64 + s] = a1[jj];
        }
        return;
    }
    if (blockIdx.x == EMBW_BLOCKS) {
        const float* Ws[3] = {Wh0, Wx1, Wh1};
        for (int i = tid; i < 3 * 64 * 64; i += 256) {
            int w = i >> 12, r = i & 4095;
            int k = r >> 6, n = r & 63;
            __nv_bfloat16 v = __float2bfloat16(Ws[w][r]);
            g_wsm[w * 64 * WSTRIDE + n * WSTRIDE + k] = *reinterpret_cast<uint16_t*>(&v);
        }
        return;
    }
    int b = (blockIdx.x - EMBW_BLOCKS - 1) * 256 + tid;
    if (b < B) {
        #pragma unroll
        for (int s = 0; s < SEQ; ++s)
            g_tokT[s * B + b] = tokens[b * SEQ + s];
    }
}

// ---------------------------------------------------------------------------
// PTX helpers (verified)
// ---------------------------------------------------------------------------
__device__ __forceinline__ void mma16816(float& d0, float& d1, float& d2, float& d3,
                                         uint32_t a0, uint32_t a1, uint32_t a2, uint32_t a3,
                                         uint32_t b0, uint32_t b1) {
    asm("mma.sync.aligned.m16n8k16.row.col.f32.bf16.bf16.f32 "
        "{%0,%1,%2,%3},{%4,%5,%6,%7},{%8,%9},{%0,%1,%2,%3};"
        : "+f"(d0), "+f"(d1), "+f"(d2), "+f"(d3)
        : "r"(a0), "r"(a1), "r"(a2), "r"(a3), "r"(b0), "r"(b1));
}

__device__ __forceinline__ void ldsm4(uint32_t& x, uint32_t& y, uint32_t& z, uint32_t& w,
                                      uint32_t saddr) {
    asm volatile("ldmatrix.sync.aligned.m8n8.x4.shared.b16 {%0,%1,%2,%3}, [%4];"
                 : "=r"(x), "=r"(y), "=r"(z), "=r"(w) : "r"(saddr));
}

__device__ __forceinline__ uint32_t packbf(float lo, float hi) {
    uint32_t r;
    asm("cvt.rn.bf16x2.f32 %0, %1, %2;" : "=r"(r) : "f"(hi), "f"(lo));
    return r;
}

__device__ __forceinline__ uint32_t tanh_bf16x2(uint32_t v) {
    uint32_t r;
    asm("tanh.approx.bf16x2 %0, %1;" : "=r"(r) : "r"(v));
    return r;
}

__device__ __forceinline__ float fast_tanh(float x) {
    float y;
    asm("tanh.approx.f32 %0, %1;" : "=f"(y) : "f"(x));
    return y;
}

// acc[32] -> h[16] A-frag words (verified mapping), tanh applied
__device__ __forceinline__ void tanh_frags(const float* acc, uint32_t* h) {
    #pragma unroll
    for (int k = 0; k < 4; ++k) {
        h[k*4+0] = tanh_bf16x2(packbf(acc[4*k],      acc[4*k+1]));
        h[k*4+1] = tanh_bf16x2(packbf(acc[16+4*k],   acc[16+4*k+1]));
        h[k*4+2] = tanh_bf16x2(packbf(acc[4*k+2],    acc[4*k+3]));
        h[k*4+3] = tanh_bf16x2(packbf(acc[16+4*k+2], acc[16+4*k+3]));
    }
}

// ---------------------------------------------------------------------------
// Kernel 2: bf16 recurrence, ONE warp per CTA, SINGLE-WALL software pipeline.
// Loop invariant at top: accA = gather(t) + h0(t-1)@Wh0 (complete pre-act).
// Body: tanh->h0f ; reload accA with gather(t+1) ; one fused 96-MMA block
//   [Wh1 (regs) -> Wx1 (ldsm) -> Wh0 (regs, LDG covered)] ; tanh->h1f.
// Wh0 fully hoisted (64 words), Wh1 kp0 + kp1.nt<4 hoisted (48 words).
// ---------------------------------------------------------------------------
__global__ void __launch_bounds__(32, 7) rnn_kernel(
    const float* __restrict__ b1,
    const float* __restrict__ Wout,
    const float* __restrict__ bout,
    float*       __restrict__ out,
    int B) {
    __shared__ __align__(16) uint16_t sW[3 * 64 * WSTRIDE];
    __shared__ float sB1[64];

    // preamble: copy pre-swizzled weight image; stage b1 permuted
    {
        const uint4* src = reinterpret_cast<const uint4*>(g_wsm);
        uint4* dst = reinterpret_cast<uint4*>(sW);
        #pragma unroll 6
        for (int i = threadIdx.x; i < 3 * 64 * WSTRIDE / 8; i += 32) dst[i] = src[i];
    }
    #pragma unroll
    for (int idx = threadIdx.x; idx < 64; idx += 32) {
        int tq_ = idx >> 4, r = idx & 15;
        int nt = r >> 1, e = r & 1;
        sB1[idx] = b1[8 * nt + 2 * tq_ + e];
    }
    __syncwarp();

    const int lane = threadIdx.x;
    const int g  = lane >> 2;
    const int tq = lane & 3;
    const int base = blockIdx.x * 16;

    int rc[2];
    #pragma unroll
    for (int i = 0; i < 2; ++i) {
        int r = base + g + 8 * i;
        rc[i] = r < B ? r : (B - 1);
    }

    // ldmatrix addressing (verified)
    const int laneoff = (lane & 7) * WSTRIDE + (lane >> 3) * 8;
    uint32_t swb = (uint32_t)__cvta_generic_to_shared(sW);
    const uint32_t aW0 = swb + 2 * laneoff;                    // Wh0
    const uint32_t aW1 = aW0 + 2 * (64 * WSTRIDE);             // Wx1
    const uint32_t aW2 = aW1 + 2 * (64 * WSTRIDE);             // Wh1

    // ---- hoist Wh0 fully (64) + Wh1 kp=0 (32) + Wh1 kp=1 nt<4 (16) ----
    uint32_t wf0[64];   // [(kp*8+nt)*4 + q]
    uint32_t wf2[48];   // kp=0: [nt*4+q] ; kp=1 nt<4: [32 + nt*4 + q]
    #pragma unroll
    for (int kp = 0; kp < 2; ++kp) {
        #pragma unroll
        for (int nt = 0; nt < 8; ++nt) {
            uint32_t off = 2 * (uint32_t)(nt * 8 * WSTRIDE + kp * 32);
            int bi = (kp * 8 + nt) * 4;
            ldsm4(wf0[bi + 0], wf0[bi + 1], wf0[bi + 2], wf0[bi + 3], aW0 + off);
        }
    }
    #pragma unroll
    for (int nt = 0; nt < 8; ++nt) {
        uint32_t off = 2 * (uint32_t)(nt * 8 * WSTRIDE);
        ldsm4(wf2[nt*4 + 0], wf2[nt*4 + 1], wf2[nt*4 + 2], wf2[nt*4 + 3], aW2 + off);
    }
    #pragma unroll
    for (int nt = 0; nt < 4; ++nt) {
        uint32_t off = 2 * (uint32_t)(nt * 8 * WSTRIDE + 32);
        ldsm4(wf2[32 + nt*4 + 0], wf2[32 + nt*4 + 1],
              wf2[32 + nt*4 + 2], wf2[32 + nt*4 + 3], aW2 + off);
    }

    float    accA[32], accB[32];   // [i(2)][nt(8)][e(2)]
    uint32_t h0f[16], h1f[16];     // A-frags [k(4)][q(4)]
    #pragma unroll
    for (int i = 0; i < 16; ++i) { h0f[i] = 0u; h1f[i] = 0u; }

    // step-0: accA = gather(0)  (h0(-1)=0 so pre-act = gather exactly)
    #pragma unroll
    for (int i = 0; i < 2; ++i) {
        int tok = g_tokT[rc[i]];
        const float4* rowp = reinterpret_cast<const float4*>(g_embW0 + tok * 64 + tq * 16);
        #pragma unroll
        for (int f = 0; f < 4; ++f) {
            float4 v = rowp[f];
            accA[i*16 + f*4 + 0] = v.x;
            accA[i*16 + f*4 + 1] = v.y;
            accA[i*16 + f*4 + 2] = v.z;
            accA[i*16 + f*4 + 3] = v.w;
        }
    }

    const float4* bp = reinterpret_cast<const float4*>(sB1 + tq * 16);

    #pragma unroll 1
    for (int ts = 0; ts < SEQ; ++ts) {
        // ---- single dependency wall: h0(t) = tanh(accA) ----
        tanh_frags(accA, h0f);

        // reload accA with gather(t+1); LDGs covered by the 64 accB MMAs below
        int tsn = (ts + 1 < SEQ) ? ts + 1 : SEQ - 1;
        #pragma unroll
        for (int i = 0; i < 2; ++i) {
            int tok = g_tokT[tsn * B + rc[i]];
            const float4* rowp =
                reinterpret_cast<const float4*>(g_embW0 + tok * 64 + tq * 16);
            #pragma unroll
            for (int f = 0; f < 4; ++f) {
                float4 v = rowp[f];
                accA[i*16 + f*4 + 0] = v.x;
                accA[i*16 + f*4 + 1] = v.y;
                accA[i*16 + f*4 + 2] = v.z;
                accA[i*16 + f*4 + 3] = v.w;
            }
        }

        // accB = b1 (4 broadcast LDS.128)
        #pragma unroll
        for (int f = 0; f < 4; ++f) {
            float4 bv = bp[f];
            accB[f*4+0] = bv.x; accB[f*4+1] = bv.y;
            accB[f*4+2] = bv.z; accB[f*4+3] = bv.w;
            accB[16+f*4+0] = bv.x; accB[16+f*4+1] = bv.y;
            accB[16+f*4+2] = bv.z; accB[16+f*4+3] = bv.w;
        }

        // ===== fused 96-MMA block (no walls inside) =====
        // (1) accB += h1(t-1) @ Wh1  — register operands (44/48) start instantly
        #pragma unroll
        for (int kp = 0; kp < 2; ++kp) {
            #pragma unroll
            for (int nt = 0; nt < 8; ++nt) {
                int k0 = 2 * kp;
                uint32_t bx, by, bz, bw;
                if (kp == 0) {
                    bx = wf2[nt*4 + 0]; by = wf2[nt*4 + 1];
                    bz = wf2[nt*4 + 2]; bw = wf2[nt*4 + 3];
                } else if (nt < 4) {
                    bx = wf2[32 + nt*4 + 0]; by = wf2[32 + nt*4 + 1];
                    bz = wf2[32 + nt*4 + 2]; bw = wf2[32 + nt*4 + 3];
                } else {
                    uint32_t off = 2 * (uint32_t)(nt * 8 * WSTRIDE + 32);
                    ldsm4(bx, by, bz, bw, aW2 + off);
                }
                mma16816(accB[nt*2], accB[nt*2+1], accB[16+nt*2], accB[16+nt*2+1],
                         h1f[k0*4+0], h1f[k0*4+1], h1f[k0*4+2], h1f[k0*4+3],
                         bx, by);
                mma16816(accB[nt*2], accB[nt*2+1], accB[16+nt*2], accB[16+nt*2+1],
                         h1f[(k0+1)*4+0], h1f[(k0+1)*4+1], h1f[(k0+1)*4+2], h1f[(k0+1)*4+3],
                         bz, bw);
            }
        }
        // (2) accB += h0(t) @ Wx1  (16 ldsm.x4)
        #pragma unroll
        for (int kp = 0; kp < 2; ++kp) {
            #pragma unroll
            for (int nt = 0; nt < 8; ++nt) {
                uint32_t off = 2 * (uint32_t)(nt * 8 * WSTRIDE + kp * 32);
                uint32_t x1, y1, z1, w1;
                ldsm4(x1, y1, z1, w1, aW1 + off);
                int k0 = 2 * kp;
                mma16816(accB[nt*2], accB[nt*2+1], accB[16+nt*2], accB[16+nt*2+1],
                         h0f[k0*4+0], h0f[k0*4+1], h0f[k0*4+2], h0f[k0*4+3], x1, y1);
                mma16816(accB[nt*2], accB[nt*2+1], accB[16+nt*2], accB[16+nt*2+1],
                         h0f[(k0+1)*4+0], h0f[(k0+1)*4+1], h0f[(k0+1)*4+2], h0f[(k0+1)*4+3],
                         z1, w1);
            }
        }
        // (3) accA(t+1) += h0(t) @ Wh0 — all regs; gather LDGs landed by now
        #pragma unroll
        for (int kp = 0; kp < 2; ++kp) {
            #pragma unroll
            for (int nt = 0; nt < 8; ++nt) {
                int bi = (kp * 8 + nt) * 4;
                int k0 = 2 * kp;
                mma16816(accA[nt*2], accA[nt*2+1], accA[16+nt*2], accA[16+nt*2+1],
                         h0f[k0*4+0], h0f[k0*4+1], h0f[k0*4+2], h0f[k0*4+3],
                         wf0[bi + 0], wf0[bi + 1]);
                mma16816(accA[nt*2], accA[nt*2+1], accA[16+nt*2], accA[16+nt*2+1],
                         h0f[(k0+1)*4+0], h0f[(k0+1)*4+1], h0f[(k0+1)*4+2], h0f[(k0+1)*4+3],
                         wf0[bi + 2], wf0[bi + 3]);
            }
        }

        // h1(t) = tanh(accB) — accB chain ended 32 MMAs ago (latency covered)
        tanh_frags(accB, h1f);
    }

    // ---- head: sigmoid(tanh(accB) @ Wout + bout), fp32 tanh on final step ----
    float wo[16];
    #pragma unroll
    for (int nt = 0; nt < 8; ++nt) {
        float2 v = *reinterpret_cast<const float2*>(Wout + nt * 8 + tq * 2);
        wo[nt * 2] = v.x; wo[nt * 2 + 1] = v.y;
    }
    float bo = bout[0];
    #pragma unroll
    for (int i = 0; i < 2; ++i) {
        float s = 0.f;
        #pragma unroll
        for (int nt = 0; nt < 8; ++nt) {
            s += fast_tanh(accB[i * 16 + nt * 2])     * wo[nt * 2];
            s += fast_tanh(accB[i * 16 + nt * 2 + 1]) * wo[nt * 2 + 1];
        }
        s += __shfl_xor_sync(0xffffffffu, s, 1);
        s += __shfl_xor_sync(0xffffffffu, s, 2);
        int r = base + g + 8 * i;
        if (tq == 0 && r < B)
            out[r] = 1.0f / (1.0f + __expf(-(s + bo)));
    }
}

// ---------------------------------------------------------------------------
extern "C" void kernel_launch(void* const* d_in, const int* in_sizes, int n_in,
                              void* d_out, int out_size) {
    const int*   tokens = (const int*)  d_in[0];
    const float* emb    = (const float*)d_in[1];
    const float* Wx0    = (const float*)d_in[2];
    const float* Wh0    = (const float*)d_in[3];
    const float* b0     = (const float*)d_in[4];
    const float* Wx1    = (const float*)d_in[5];
    const float* Wh1    = (const float*)d_in[6];
    const float* b1     = (const float*)d_in[7];
    const float* Wout   = (const float*)d_in[8];
    const float* bout   = (const float*)d_in[9];
    float* out = (float*)d_out;

    int B = in_sizes[0] / SEQ;
    if (B > BMAX) B = BMAX;

    int prep_blocks = EMBW_BLOCKS + 1 + (B + 255) / 256;
    prep_kernel<<<prep_blocks, 256>>>(emb, Wx0, b0, Wh0, Wx1, Wh1, tokens, B);

    int nblocks = (B + 15) / 16;
    rnn_kernel<<<nblocks, 32>>>(b1, Wout, bout, out, B);
}

// round 16
// speedup vs baseline: 1.0373x; 1.0034x over previous
#include <cuda_runtime.h>
#include <cuda_bf16.h>
#include <stdint.h>

#define SEQ 80
#define EMB 100
#define VOCAB 10000
#define BMAX 16384
#define WSTRIDE 72   // padded bf16 row stride: conflict-free ldmatrix (verified)

// Precomputed emb @ Wx0 + b0 (fp32), columns permuted: col j -> slot sidx_full(j)
__device__ float g_embW0[VOCAB * 64];
// Transposed tokens [SEQ][B]
__device__ int g_tokT[SEQ * BMAX];
// Pre-swizzled bf16 weight image (exact smem layout): Wh0^T, Wx1^T, Wh1^T
__device__ uint16_t g_wsm[3 * 64 * WSTRIDE];

#define EMBW_BLOCKS 313

// storage slot of unit j: thread tq's 16 values land contiguous (verified R10)
__host__ __device__ __forceinline__ int sidx_full(int j) {
    int nt = j >> 3, tq = (j >> 1) & 3, e = j & 1;
    return 16 * tq + 2 * nt + e;
}

// ---------------------------------------------------------------------------
// Prep (fused): embW0 (fp32, permuted cols) | weight image | token transpose
// (identical to R13 — verified)
// ---------------------------------------------------------------------------
__global__ void __launch_bounds__(256) prep_kernel(const float* __restrict__ emb,
                                                   const float* __restrict__ Wx0,
                                                   const float* __restrict__ b0,
                                                   const float* __restrict__ Wh0,
                                                   const float* __restrict__ Wx1,
                                                   const float* __restrict__ Wh1,
                                                   const int*   __restrict__ tokens,
                                                   int B) {
    int tid = threadIdx.x;
    if (blockIdx.x < EMBW_BLOCKS) {
        __shared__ float sW[EMB * 64];
        __shared__ float sE[32 * EMB];
        for (int i = tid; i < EMB * 64; i += 256) sW[i] = Wx0[i];
        int vbase = blockIdx.x * 32;
        for (int i = tid; i < 32 * EMB; i += 256) {
            int r = vbase + i / EMB;
            sE[i] = emb[(r < VOCAB ? r : 0) * EMB + i % EMB];
        }
        __syncthreads();

        int tcol = tid & 15;
        int trow = tid >> 4;
        float a0[4], a1[4];
        *reinterpret_cast<float4*>(a0) = *reinterpret_cast<const float4*>(b0 + tcol * 4);
        *reinterpret_cast<float4*>(a1) = *reinterpret_cast<float4*>(a0);
        const float* e0 = sE + trow * EMB;
        const float* e1 = sE + (trow + 16) * EMB;
        const float4* sW4 = reinterpret_cast<const float4*>(sW);
        #pragma unroll 10
        for (int k = 0; k < EMB; ++k) {
            float4 w = sW4[k * 16 + tcol];
            float ev0 = e0[k], ev1 = e1[k];
            a0[0] += ev0 * w.x; a0[1] += ev0 * w.y; a0[2] += ev0 * w.z; a0[3] += ev0 * w.w;
            a1[0] += ev1 * w.x; a1[1] += ev1 * w.y; a1[2] += ev1 * w.z; a1[3] += ev1 * w.w;
        }
        int v0 = vbase + trow, v1 = vbase + trow + 16;
        #pragma unroll
        for (int jj = 0; jj < 4; ++jj) {
            int s = sidx_full(tcol * 4 + jj);
            if (v0 < VOCAB) g_embW0[v0 * 64 + s] = a0[jj];
            if (v1 < VOCAB) g_embW0[v1 * 64 + s] = a1[jj];
        }
        return;
    }
    if (blockIdx.x == EMBW_BLOCKS) {
        const float* Ws[3] = {Wh0, Wx1, Wh1};
        for (int i = tid; i < 3 * 64 * 64; i += 256) {
            int w = i >> 12, r = i & 4095;
            int k = r >> 6, n = r & 63;
            __nv_bfloat16 v = __float2bfloat16(Ws[w][r]);
            g_wsm[w * 64 * WSTRIDE + n * WSTRIDE + k] = *reinterpret_cast<uint16_t*>(&v);
        }
        return;
    }
    int b = (blockIdx.x - EMBW_BLOCKS - 1) * 256 + tid;
    if (b < B) {
        #pragma unroll
        for (int s = 0; s < SEQ; ++s)
            g_tokT[s * B + b] = tokens[b * SEQ + s];
    }
}

// ---------------------------------------------------------------------------
// PTX helpers (verified)
// ---------------------------------------------------------------------------
__device__ __forceinline__ void mma16816(float& d0, float& d1, float& d2, float& d3,
                                         uint32_t a0, uint32_t a1, uint32_t a2, uint32_t a3,
                                         uint32_t b0, uint32_t b1) {
    asm("mma.sync.aligned.m16n8k16.row.col.f32.bf16.bf16.f32 "
        "{%0,%1,%2,%3},{%4,%5,%6,%7},{%8,%9},{%0,%1,%2,%3};"
        : "+f"(d0), "+f"(d1), "+f"(d2), "+f"(d3)
        : "r"(a0), "r"(a1), "r"(a2), "r"(a3), "r"(b0), "r"(b1));
}

__device__ __forceinline__ void ldsm4(uint32_t& x, uint32_t& y, uint32_t& z, uint32_t& w,
                                      uint32_t saddr) {
    asm volatile("ldmatrix.sync.aligned.m8n8.x4.shared.b16 {%0,%1,%2,%3}, [%4];"
                 : "=r"(x), "=r"(y), "=r"(z), "=r"(w) : "r"(saddr));
}

__device__ __forceinline__ uint32_t packbf(float lo, float hi) {
    uint32_t r;
    asm("cvt.rn.bf16x2.f32 %0, %1, %2;" : "=r"(r) : "f"(hi), "f"(lo));
    return r;
}

__device__ __forceinline__ uint32_t tanh_bf16x2(uint32_t v) {
    uint32_t r;
    asm("tanh.approx.bf16x2 %0, %1;" : "=r"(r) : "r"(v));
    return r;
}

__device__ __forceinline__ float fast_tanh(float x) {
    float y;
    asm("tanh.approx.f32 %0, %1;" : "=f"(y) : "f"(x));
    return y;
}

// acc[32] -> h[16] A-frag words (verified mapping), tanh applied
__device__ __forceinline__ void tanh_frags(const float* acc, uint32_t* h) {
    #pragma unroll
    for (int k = 0; k < 4; ++k) {
        h[k*4+0] = tanh_bf16x2(packbf(acc[4*k],      acc[4*k+1]));
        h[k*4+1] = tanh_bf16x2(packbf(acc[16+4*k],   acc[16+4*k+1]));
        h[k*4+2] = tanh_bf16x2(packbf(acc[4*k+2],    acc[4*k+3]));
        h[k*4+3] = tanh_bf16x2(packbf(acc[16+4*k+2], acc[16+4*k+3]));
    }
}

// ---------------------------------------------------------------------------
// Kernel 2: bf16 recurrence, ONE warp per CTA, wall-free ordering:
//   A: accA += h0f(t-1)@Wh0 (32 reg-MMA)     [accA held gather(t)]
//   B: tanh(accA) -> h0f(t)                   [covered by C below]
//   E: gather(t+1) -> accA                    [covered by C+D]
//   C: accB = b1 + h1f(t-1)@Wh1 (32 MMA)      [covers B; h1f wall covered by A]
//   D: accB += h0f(t)@Wx1 (32 MMA, ldsm)
//   F: tanh(accB) -> h1f(t)                   [consumed at C-next, covered by A-next]
// Wh0 fully hoisted (64 words), Wh1 kp0 + kp1.nt<4 hoisted (48 words).
// ---------------------------------------------------------------------------
__global__ void __launch_bounds__(32, 7) rnn_kernel(
    const float* __restrict__ b1,
    const float* __restrict__ Wout,
    const float* __restrict__ bout,
    float*       __restrict__ out,
    int B) {
    __shared__ __align__(16) uint16_t sW[3 * 64 * WSTRIDE];
    __shared__ float sB1[64];

    // preamble: copy pre-swizzled weight image; stage b1 permuted
    {
        const uint4* src = reinterpret_cast<const uint4*>(g_wsm);
        uint4* dst = reinterpret_cast<uint4*>(sW);
        #pragma unroll 6
        for (int i = threadIdx.x; i < 3 * 64 * WSTRIDE / 8; i += 32) dst[i] = src[i];
    }
    #pragma unroll
    for (int idx = threadIdx.x; idx < 64; idx += 32) {
        int tq_ = idx >> 4, r = idx & 15;
        int nt = r >> 1, e = r & 1;
        sB1[idx] = b1[8 * nt + 2 * tq_ + e];
    }
    __syncwarp();

    const int lane = threadIdx.x;
    const int g  = lane >> 2;
    const int tq = lane & 3;
    const int base = blockIdx.x * 16;

    int rc[2];
    #pragma unroll
    for (int i = 0; i < 2; ++i) {
        int r = base + g + 8 * i;
        rc[i] = r < B ? r : (B - 1);
    }

    // ldmatrix addressing (verified)
    const int laneoff = (lane & 7) * WSTRIDE + (lane >> 3) * 8;
    uint32_t swb = (uint32_t)__cvta_generic_to_shared(sW);
    const uint32_t aW0 = swb + 2 * laneoff;                    // Wh0
    const uint32_t aW1 = aW0 + 2 * (64 * WSTRIDE);             // Wx1
    const uint32_t aW2 = aW1 + 2 * (64 * WSTRIDE);             // Wh1

    // ---- hoist Wh0 fully (64) + Wh1 kp=0 (32) + Wh1 kp=1 nt<4 (16) ----
    uint32_t wf0[64];   // [(kp*8+nt)*4 + q]
    uint32_t wf2[48];   // kp=0: [nt*4+q] ; kp=1 nt<4: [32 + nt*4 + q]
    #pragma unroll
    for (int kp = 0; kp < 2; ++kp) {
        #pragma unroll
        for (int nt = 0; nt < 8; ++nt) {
            uint32_t off = 2 * (uint32_t)(nt * 8 * WSTRIDE + kp * 32);
            int bi = (kp * 8 + nt) * 4;
            ldsm4(wf0[bi + 0], wf0[bi + 1], wf0[bi + 2], wf0[bi + 3], aW0 + off);
        }
    }
    #pragma unroll
    for (int nt = 0; nt < 8; ++nt) {
        uint32_t off = 2 * (uint32_t)(nt * 8 * WSTRIDE);
        ldsm4(wf2[nt*4 + 0], wf2[nt*4 + 1], wf2[nt*4 + 2], wf2[nt*4 + 3], aW2 + off);
    }
    #pragma unroll
    for (int nt = 0; nt < 4; ++nt) {
        uint32_t off = 2 * (uint32_t)(nt * 8 * WSTRIDE + 32);
        ldsm4(wf2[32 + nt*4 + 0], wf2[32 + nt*4 + 1],
              wf2[32 + nt*4 + 2], wf2[32 + nt*4 + 3], aW2 + off);
    }

    float    accA[32], accB[32];   // [i(2)][nt(8)][e(2)]
    uint32_t h0f[16], h1f[16];     // A-frags [k(4)][q(4)]
    #pragma unroll
    for (int i = 0; i < 16; ++i) { h0f[i] = 0u; h1f[i] = 0u; }

    // step-0: accA = gather(0)
    #pragma unroll
    for (int i = 0; i < 2; ++i) {
        int tok = g_tokT[rc[i]];
        const float4* rowp = reinterpret_cast<const float4*>(g_embW0 + tok * 64 + tq * 16);
        #pragma unroll
        for (int f = 0; f < 4; ++f) {
            float4 v = rowp[f];
            accA[i*16 + f*4 + 0] = v.x;
            accA[i*16 + f*4 + 1] = v.y;
            accA[i*16 + f*4 + 2] = v.z;
            accA[i*16 + f*4 + 3] = v.w;
        }
    }

    const float4* bp = reinterpret_cast<const float4*>(sB1 + tq * 16);

    #pragma unroll 1
    for (int ts = 0; ts < SEQ; ++ts) {
        // ---- A: accA += h0f(t-1) @ Wh0  (32 MMA, all-register) ----
        #pragma unroll
        for (int kp = 0; kp < 2; ++kp) {
            #pragma unroll
            for (int nt = 0; nt < 8; ++nt) {
                int bi = (kp * 8 + nt) * 4;
                int k0 = 2 * kp;
                mma16816(accA[nt*2], accA[nt*2+1], accA[16+nt*2], accA[16+nt*2+1],
                         h0f[k0*4+0], h0f[k0*4+1], h0f[k0*4+2], h0f[k0*4+3],
                         wf0[bi + 0], wf0[bi + 1]);
                mma16816(accA[nt*2], accA[nt*2+1], accA[16+nt*2], accA[16+nt*2+1],
                         h0f[(k0+1)*4+0], h0f[(k0+1)*4+1], h0f[(k0+1)*4+2], h0f[(k0+1)*4+3],
                         wf0[bi + 2], wf0[bi + 3]);
            }
        }

        // ---- B: h0f(t) = tanh(accA); scheduler overlaps with C below ----
        tanh_frags(accA, h0f);

        // ---- E: gather(t+1) -> accA (LDGs covered by C+D) ----
        int tsn = (ts + 1 < SEQ) ? ts + 1 : SEQ - 1;
        #pragma unroll
        for (int i = 0; i < 2; ++i) {
            int tok = g_tokT[tsn * B + rc[i]];
            const float4* rowp =
                reinterpret_cast<const float4*>(g_embW0 + tok * 64 + tq * 16);
            #pragma unroll
            for (int f = 0; f < 4; ++f) {
                float4 v = rowp[f];
                accA[i*16 + f*4 + 0] = v.x;
                accA[i*16 + f*4 + 1] = v.y;
                accA[i*16 + f*4 + 2] = v.z;
                accA[i*16 + f*4 + 3] = v.w;
            }
        }

        // ---- C: accB = b1 + h1f(t-1) @ Wh1  (32 MMA; covers tanh in B) ----
        #pragma unroll
        for (int f = 0; f < 4; ++f) {
            float4 bv = bp[f];
            accB[f*4+0] = bv.x; accB[f*4+1] = bv.y;
            accB[f*4+2] = bv.z; accB[f*4+3] = bv.w;
            accB[16+f*4+0] = bv.x; accB[16+f*4+1] = bv.y;
            accB[16+f*4+2] = bv.z; accB[16+f*4+3] = bv.w;
        }
        #pragma unroll
        for (int kp = 0; kp < 2; ++kp) {
            #pragma unroll
            for (int nt = 0; nt < 8; ++nt) {
                int k0 = 2 * kp;
                uint32_t bx, by, bz, bw;
                if (kp == 0) {
                    bx = wf2[nt*4 + 0]; by = wf2[nt*4 + 1];
                    bz = wf2[nt*4 + 2]; bw = wf2[nt*4 + 3];
                } else if (nt < 4) {
                    bx = wf2[32 + nt*4 + 0]; by = wf2[32 + nt*4 + 1];
                    bz = wf2[32 + nt*4 + 2]; bw = wf2[32 + nt*4 + 3];
                } else {
                    uint32_t off = 2 * (uint32_t)(nt * 8 * WSTRIDE + 32);
                    ldsm4(bx, by, bz, bw, aW2 + off);
                }
                mma16816(accB[nt*2], accB[nt*2+1], accB[16+nt*2], accB[16+nt*2+1],
                         h1f[k0*4+0], h1f[k0*4+1], h1f[k0*4+2], h1f[k0*4+3],
                         bx, by);
                mma16816(accB[nt*2], accB[nt*2+1], accB[16+nt*2], accB[16+nt*2+1],
                         h1f[(k0+1)*4+0], h1f[(k0+1)*4+1], h1f[(k0+1)*4+2], h1f[(k0+1)*4+3],
                         bz, bw);
            }
        }

        // ---- D: accB += h0f(t) @ Wx1  (32 MMA, 16 ldsm) ----
        #pragma unroll
        for (int kp = 0; kp < 2; ++kp) {
            #pragma unroll
            for (int nt = 0; nt < 8; ++nt) {
                uint32_t off = 2 * (uint32_t)(nt * 8 * WSTRIDE + kp * 32);
                uint32_t x1, y1, z1, w1;
                ldsm4(x1, y1, z1, w1, aW1 + off);
                int k0 = 2 * kp;
                mma16816(accB[nt*2], accB[nt*2+1], accB[16+nt*2], accB[16+nt*2+1],
                         h0f[k0*4+0], h0f[k0*4+1], h0f[k0*4+2], h0f[k0*4+3], x1, y1);
                mma16816(accB[nt*2], accB[nt*2+1], accB[16+nt*2], accB[16+nt*2+1],
                         h0f[(k0+1)*4+0], h0f[(k0+1)*4+1], h0f[(k0+1)*4+2], h0f[(k0+1)*4+3],
                         z1, w1);
            }
        }

        // ---- F: h1f(t) = tanh(accB); consumed at C-next, covered by A-next ----
        tanh_frags(accB, h1f);
    }

    // ---- head: sigmoid(tanh(accB) @ Wout + bout), fp32 tanh on final step ----
    float wo[16];
    #pragma unroll
    for (int nt = 0; nt < 8; ++nt) {
        float2 v = *reinterpret_cast<const float2*>(Wout + nt * 8 + tq * 2);
        wo[nt * 2] = v.x; wo[nt * 2 + 1] = v.y;
    }
    float bo = bout[0];
    #pragma unroll
    for (int i = 0; i < 2; ++i) {
        float s = 0.f;
        #pragma unroll
        for (int nt = 0; nt < 8; ++nt) {
            s += fast_tanh(accB[i * 16 + nt * 2])     * wo[nt * 2];
            s += fast_tanh(accB[i * 16 + nt * 2 + 1]) * wo[nt * 2 + 1];
        }
        s += __shfl_xor_sync(0xffffffffu, s, 1);
        s += __shfl_xor_sync(0xffffffffu, s, 2);
        int r = base + g + 8 * i;
        if (tq == 0 && r < B)
            out[r] = 1.0f / (1.0f + __expf(-(s + bo)));
    }
}

// ---------------------------------------------------------------------------
extern "C" void kernel_launch(void* const* d_in, const int* in_sizes, int n_in,
                              void* d_out, int out_size) {
    const int*   tokens = (const int*)  d_in[0];
    const float* emb    = (const float*)d_in[1];
    const float* Wx0    = (const float*)d_in[2];
    const float* Wh0    = (const float*)d_in[3];
    const float* b0     = (const float*)d_in[4];
    const float* Wx1    = (const float*)d_in[5];
    const float* Wh1    = (const float*)d_in[6];
    const float* b1     = (const float*)d_in[7];
    const float* Wout   = (const float*)d_in[8];
    const float* bout   = (const float*)d_in[9];
    float* out = (float*)d_out;

    int B = in_sizes[0] / SEQ;
    if (B > BMAX) B = BMAX;

    int prep_blocks = EMBW_BLOCKS + 1 + (B + 255) / 256;
    prep_kernel<<<prep_blocks, 256>>>(emb, Wx0, b0, Wh0, Wx1, Wh1, tokens, B);

    int nblocks = (B + 15) / 16;
    rnn_kernel<<<nblocks, 32>>>(b1, Wout, bout, out, B);
}

// round 17
// speedup vs baseline: 1.0826x; 1.0436x over previous
#include <cuda_runtime.h>
#include <cuda_bf16.h>
#include <stdint.h>

#define SEQ 80
#define EMB 100
#define VOCAB 10000
#define BMAX 16384
#define WSTRIDE 72   // padded bf16 row stride: conflict-free ldmatrix (verified)

// Precomputed emb @ Wx0 + b0 (fp32), columns permuted: col j -> slot sidx_full(j)
__device__ float g_embW0[VOCAB * 64];
// Transposed tokens [SEQ][B]
__device__ int g_tokT[SEQ * BMAX];
// Pre-swizzled bf16 weight image (exact smem layout): Wh0^T, Wx1^T, Wh1^T
__device__ uint16_t g_wsm[3 * 64 * WSTRIDE];

#define EMBW_BLOCKS 157   // 64 vocab rows per block (157*64 = 10048 >= 10000)

// storage slot of unit j: thread tq's 16 values land contiguous (verified R10)
__host__ __device__ __forceinline__ int sidx_full(int j) {
    int nt = j >> 3, tq = (j >> 1) & 3, e = j & 1;
    return 16 * tq + 2 * nt + e;
}

// ---------------------------------------------------------------------------
// Prep (fused): embW0 (fp32, permuted cols, 4x4 register tiles)
//             | weight image | token transpose (smem-tiled, coalesced)
// ---------------------------------------------------------------------------
__global__ void __launch_bounds__(256) prep_kernel(const float* __restrict__ emb,
                                                   const float* __restrict__ Wx0,
                                                   const float* __restrict__ b0,
                                                   const float* __restrict__ Wh0,
                                                   const float* __restrict__ Wx1,
                                                   const float* __restrict__ Wh1,
                                                   const int*   __restrict__ tokens,
                                                   int B) {
    int tid = threadIdx.x;
    if (blockIdx.x < EMBW_BLOCKS) {
        __shared__ float sW[EMB * 64];    // [k][j]
        __shared__ float sE[64 * EMB];    // 64 vocab rows
        for (int i = tid; i < EMB * 64; i += 256) sW[i] = Wx0[i];
        int vbase = blockIdx.x * 64;
        for (int i = tid; i < 64 * EMB; i += 256) {
            int r = vbase + i / EMB;
            sE[i] = emb[(r < VOCAB ? r : 0) * EMB + i % EMB];
        }
        __syncthreads();

        int rg = tid >> 4;   // row group: rows 4*rg .. 4*rg+3
        int cg = tid & 15;   // col group: cols 4*cg .. 4*cg+3
        float a[4][4];
        {
            float4 bv = *reinterpret_cast<const float4*>(b0 + cg * 4);
            #pragma unroll
            for (int r = 0; r < 4; ++r) {
                a[r][0] = bv.x; a[r][1] = bv.y; a[r][2] = bv.z; a[r][3] = bv.w;
            }
        }
        const float4* sW4 = reinterpret_cast<const float4*>(sW);
        const float* e0 = sE + (4 * rg + 0) * EMB;
        const float* e1 = sE + (4 * rg + 1) * EMB;
        const float* e2 = sE + (4 * rg + 2) * EMB;
        const float* e3 = sE + (4 * rg + 3) * EMB;
        #pragma unroll 5
        for (int k = 0; k < EMB; ++k) {
            float4 w = sW4[k * 16 + cg];
            float v0 = e0[k], v1 = e1[k], v2 = e2[k], v3 = e3[k];
            a[0][0] += v0 * w.x; a[0][1] += v0 * w.y; a[0][2] += v0 * w.z; a[0][3] += v0 * w.w;
            a[1][0] += v1 * w.x; a[1][1] += v1 * w.y; a[1][2] += v1 * w.z; a[1][3] += v1 * w.w;
            a[2][0] += v2 * w.x; a[2][1] += v2 * w.y; a[2][2] += v2 * w.z; a[2][3] += v2 * w.w;
            a[3][0] += v3 * w.x; a[3][1] += v3 * w.y; a[3][2] += v3 * w.z; a[3][3] += v3 * w.w;
        }
        #pragma unroll
        for (int r = 0; r < 4; ++r) {
            int v = vbase + 4 * rg + r;
            if (v < VOCAB) {
                #pragma unroll
                for (int jj = 0; jj < 4; ++jj)
                    g_embW0[v * 64 + sidx_full(cg * 4 + jj)] = a[r][jj];
            }
        }
        return;
    }
    if (blockIdx.x == EMBW_BLOCKS) {
        const float* Ws[3] = {Wh0, Wx1, Wh1};
        for (int i = tid; i < 3 * 64 * 64; i += 256) {
            int w = i >> 12, r = i & 4095;
            int k = r >> 6, n = r & 63;
            __nv_bfloat16 v = __float2bfloat16(Ws[w][r]);
            g_wsm[w * 64 * WSTRIDE + n * WSTRIDE + k] = *reinterpret_cast<uint16_t*>(&v);
        }
        return;
    }
    // token transpose: 32 batch rows per block, smem-tiled (stride 81 pad)
    {
        __shared__ int sT[32 * 81];
        int b0r = (blockIdx.x - EMBW_BLOCKS - 1) * 32;
        for (int i = tid; i < 32 * SEQ; i += 256) {
            int lb = i / SEQ, s = i % SEQ;
            int b = b0r + lb;
            sT[lb * 81 + s] = (b < B) ? tokens[b * SEQ + s] : 0;
        }
        __syncthreads();
        for (int i = tid; i < SEQ * 32; i += 256) {
            int s = i >> 5, lb = i & 31;
            int b = b0r + lb;
            if (b < B) g_tokT[s * B + b] = sT[lb * 81 + s];
        }
    }
}

// ---------------------------------------------------------------------------
// PTX helpers (verified)
// ---------------------------------------------------------------------------
__device__ __forceinline__ void mma16816(float& d0, float& d1, float& d2, float& d3,
                                         uint32_t a0, uint32_t a1, uint32_t a2, uint32_t a3,
                                         uint32_t b0, uint32_t b1) {
    asm("mma.sync.aligned.m16n8k16.row.col.f32.bf16.bf16.f32 "
        "{%0,%1,%2,%3},{%4,%5,%6,%7},{%8,%9},{%0,%1,%2,%3};"
        : "+f"(d0), "+f"(d1), "+f"(d2), "+f"(d3)
        : "r"(a0), "r"(a1), "r"(a2), "r"(a3), "r"(b0), "r"(b1));
}

__device__ __forceinline__ void ldsm4(uint32_t& x, uint32_t& y, uint32_t& z, uint32_t& w,
                                      uint32_t saddr) {
    asm volatile("ldmatrix.sync.aligned.m8n8.x4.shared.b16 {%0,%1,%2,%3}, [%4];"
                 : "=r"(x), "=r"(y), "=r"(z), "=r"(w) : "r"(saddr));
}

__device__ __forceinline__ uint32_t packbf(float lo, float hi) {
    uint32_t r;
    asm("cvt.rn.bf16x2.f32 %0, %1, %2;" : "=r"(r) : "f"(hi), "f"(lo));
    return r;
}

__device__ __forceinline__ uint32_t tanh_bf16x2(uint32_t v) {
    uint32_t r;
    asm("tanh.approx.bf16x2 %0, %1;" : "=r"(r) : "r"(v));
    return r;
}

__device__ __forceinline__ float fast_tanh(float x) {
    float y;
    asm("tanh.approx.f32 %0, %1;" : "=f"(y) : "f"(x));
    return y;
}

// acc[32] -> h[16] A-frag words (verified mapping), tanh applied
__device__ __forceinline__ void tanh_frags(const float* acc, uint32_t* h) {
    #pragma unroll
    for (int k = 0; k < 4; ++k) {
        h[k*4+0] = tanh_bf16x2(packbf(acc[4*k],      acc[4*k+1]));
        h[k*4+1] = tanh_bf16x2(packbf(acc[16+4*k],   acc[16+4*k+1]));
        h[k*4+2] = tanh_bf16x2(packbf(acc[4*k+2],    acc[4*k+3]));
        h[k*4+3] = tanh_bf16x2(packbf(acc[16+4*k+2], acc[16+4*k+3]));
    }
}

// ---------------------------------------------------------------------------
// Kernel 2: bf16 recurrence, ONE warp per CTA — EXACT R13 body (best total).
// Wh0 fully hoisted (64 words), Wh1 half-hoisted (kp=0, 32 words);
// Wh1 kp=1 (8 ldsm) + Wx1 (16 ldsm) read per step. grid = B/16 = 1024.
// ---------------------------------------------------------------------------
__global__ void __launch_bounds__(32, 7) rnn_kernel(
    const float* __restrict__ b1,
    const float* __restrict__ Wout,
    const float* __restrict__ bout,
    float*       __restrict__ out,
    int B) {
    __shared__ __align__(16) uint16_t sW[3 * 64 * WSTRIDE];
    __shared__ float sB1[64];

    // preamble: copy pre-swizzled weight image; stage b1 permuted
    {
        const uint4* src = reinterpret_cast<const uint4*>(g_wsm);
        uint4* dst = reinterpret_cast<uint4*>(sW);
        #pragma unroll 6
        for (int i = threadIdx.x; i < 3 * 64 * WSTRIDE / 8; i += 32) dst[i] = src[i];
    }
    #pragma unroll
    for (int idx = threadIdx.x; idx < 64; idx += 32) {
        int tq_ = idx >> 4, r = idx & 15;
        int nt = r >> 1, e = r & 1;
        sB1[idx] = b1[8 * nt + 2 * tq_ + e];
    }
    __syncwarp();

    const int lane = threadIdx.x;
    const int g  = lane >> 2;
    const int tq = lane & 3;
    const int base = blockIdx.x * 16;

    int rc[2];
    #pragma unroll
    for (int i = 0; i < 2; ++i) {
        int r = base + g + 8 * i;
        rc[i] = r < B ? r : (B - 1);
    }

    // ldmatrix addressing (verified)
    const int laneoff = (lane & 7) * WSTRIDE + (lane >> 3) * 8;
    uint32_t swb = (uint32_t)__cvta_generic_to_shared(sW);
    const uint32_t aW0 = swb + 2 * laneoff;                    // Wh0
    const uint32_t aW1 = aW0 + 2 * (64 * WSTRIDE);             // Wx1
    const uint32_t aW2 = aW1 + 2 * (64 * WSTRIDE);             // Wh1

    // ---- hoist Wh0 fully (64 words) + Wh1 kp=0 half (32 words) ----
    uint32_t wf0[64];   // [(kp*8+nt)*4 + {x,y,z,w}]
    uint32_t wf2[32];   // [nt*4 + {x,y,z,w}]  (kp=0 only)
    #pragma unroll
    for (int kp = 0; kp < 2; ++kp) {
        #pragma unroll
        for (int nt = 0; nt < 8; ++nt) {
            uint32_t off = 2 * (uint32_t)(nt * 8 * WSTRIDE + kp * 32);
            int bi = (kp * 8 + nt) * 4;
            ldsm4(wf0[bi + 0], wf0[bi + 1], wf0[bi + 2], wf0[bi + 3], aW0 + off);
        }
    }
    #pragma unroll
    for (int nt = 0; nt < 8; ++nt) {
        uint32_t off = 2 * (uint32_t)(nt * 8 * WSTRIDE);
        ldsm4(wf2[nt*4 + 0], wf2[nt*4 + 1], wf2[nt*4 + 2], wf2[nt*4 + 3], aW2 + off);
    }

    float    accA[32], accB[32];   // [i(2)][nt(8)][e(2)]
    uint32_t h0f[16], h1f[16];     // A-frags [k(4)][q(4)]
    #pragma unroll
    for (int i = 0; i < 16; ++i) { h0f[i] = 0u; h1f[i] = 0u; }

    // step-0 gather: 16 contiguous floats per lane per row
    #pragma unroll
    for (int i = 0; i < 2; ++i) {
        int tok = g_tokT[rc[i]];
        const float4* rowp = reinterpret_cast<const float4*>(g_embW0 + tok * 64 + tq * 16);
        #pragma unroll
        for (int f = 0; f < 4; ++f) {
            float4 v = rowp[f];
            accA[i*16 + f*4 + 0] = v.x;
            accA[i*16 + f*4 + 1] = v.y;
            accA[i*16 + f*4 + 2] = v.z;
            accA[i*16 + f*4 + 3] = v.w;
        }
    }

    const float4* bp = reinterpret_cast<const float4*>(sB1 + tq * 16);

    #pragma unroll 1
    for (int ts = 0; ts < SEQ; ++ts) {
        int tsn = (ts + 1 < SEQ) ? ts + 1 : SEQ - 1;
        int tkn[2];
        #pragma unroll
        for (int i = 0; i < 2; ++i) tkn[i] = g_tokT[tsn * B + rc[i]];

        // accB = b1 (4 broadcast LDS.128)
        #pragma unroll
        for (int f = 0; f < 4; ++f) {
            float4 bv = bp[f];
            accB[f*4+0] = bv.x; accB[f*4+1] = bv.y;
            accB[f*4+2] = bv.z; accB[f*4+3] = bv.w;
            accB[16+f*4+0] = bv.x; accB[16+f*4+1] = bv.y;
            accB[16+f*4+2] = bv.z; accB[16+f*4+3] = bv.w;
        }

        // recurrent GEMM pair: accA += h0 @ Wh0 (regs) ; accB += h1 @ Wh1
        // (kp=0 from regs; kp=1 via 4 ldsm issued inline)
        #pragma unroll
        for (int kp = 0; kp < 2; ++kp) {
            #pragma unroll
            for (int nt = 0; nt < 8; ++nt) {
                int bi = (kp * 8 + nt) * 4;
                int k0 = 2 * kp;
                uint32_t bx, by, bz, bw;
                if (kp == 0) {
                    bx = wf2[nt*4 + 0]; by = wf2[nt*4 + 1];
                    bz = wf2[nt*4 + 2]; bw = wf2[nt*4 + 3];
                } else {
                    uint32_t off = 2 * (uint32_t)(nt * 8 * WSTRIDE + 32);
                    ldsm4(bx, by, bz, bw, aW2 + off);
                }
                mma16816(accA[nt*2], accA[nt*2+1], accA[16+nt*2], accA[16+nt*2+1],
                         h0f[k0*4+0], h0f[k0*4+1], h0f[k0*4+2], h0f[k0*4+3],
                         wf0[bi + 0], wf0[bi + 1]);
                mma16816(accB[nt*2], accB[nt*2+1], accB[16+nt*2], accB[16+nt*2+1],
                         h1f[k0*4+0], h1f[k0*4+1], h1f[k0*4+2], h1f[k0*4+3],
                         bx, by);
                mma16816(accA[nt*2], accA[nt*2+1], accA[16+nt*2], accA[16+nt*2+1],
                         h0f[(k0+1)*4+0], h0f[(k0+1)*4+1], h0f[(k0+1)*4+2], h0f[(k0+1)*4+3],
                         wf0[bi + 2], wf0[bi + 3]);
                mma16816(accB[nt*2], accB[nt*2+1], accB[16+nt*2], accB[16+nt*2+1],
                         h1f[(k0+1)*4+0], h1f[(k0+1)*4+1], h1f[(k0+1)*4+2], h1f[(k0+1)*4+3],
                         bz, bw);
            }
        }

        // h0 = tanh(accA) -> A-frags
        tanh_frags(accA, h0f);

        // prefetch next-step gather into accA (covers L2 latency over layer 1)
        #pragma unroll
        for (int i = 0; i < 2; ++i) {
            const float4* rowp =
                reinterpret_cast<const float4*>(g_embW0 + tkn[i] * 64 + tq * 16);
            #pragma unroll
            for (int f = 0; f < 4; ++f) {
                float4 v = rowp[f];
                accA[i*16 + f*4 + 0] = v.x;
                accA[i*16 + f*4 + 1] = v.y;
                accA[i*16 + f*4 + 2] = v.z;
                accA[i*16 + f*4 + 3] = v.w;
            }
        }

        // accB += h0new @ Wx1 (16 ldsm.x4)
        #pragma unroll
        for (int kp = 0; kp < 2; ++kp) {
            #pragma unroll
            for (int nt = 0; nt < 8; ++nt) {
                uint32_t off = 2 * (uint32_t)(nt * 8 * WSTRIDE + kp * 32);
                uint32_t x1, y1, z1, w1;
                ldsm4(x1, y1, z1, w1, aW1 + off);
                int k0 = 2 * kp;
                mma16816(accB[nt*2], accB[nt*2+1], accB[16+nt*2], accB[16+nt*2+1],
                         h0f[k0*4+0], h0f[k0*4+1], h0f[k0*4+2], h0f[k0*4+3], x1, y1);
                mma16816(accB[nt*2], accB[nt*2+1], accB[16+nt*2], accB[16+nt*2+1],
                         h0f[(k0+1)*4+0], h0f[(k0+1)*4+1], h0f[(k0+1)*4+2], h0f[(k0+1)*4+3],
                         z1, w1);
            }
        }

        // h1 = tanh(accB) -> A-frags
        tanh_frags(accB, h1f);
    }

    // ---- head: sigmoid(tanh(accB) @ Wout + bout), fp32 tanh on final step ----
    float wo[16];
    #pragma unroll
    for (int nt = 0; nt < 8; ++nt) {
        float2 v = *reinterpret_cast<const float2*>(Wout + nt * 8 + tq * 2);
        wo[nt * 2] = v.x; wo[nt * 2 + 1] = v.y;
    }
    float bo = bout[0];
    #pragma unroll
    for (int i = 0; i < 2; ++i) {
        float s = 0.f;
        #pragma unroll
        for (int nt = 0; nt < 8; ++nt) {
            s += fast_tanh(accB[i * 16 + nt * 2])     * wo[nt * 2];
            s += fast_tanh(accB[i * 16 + nt * 2 + 1]) * wo[nt * 2 + 1];
        }
        s += __shfl_xor_sync(0xffffffffu, s, 1);
        s += __shfl_xor_sync(0xffffffffu, s, 2);
        int r = base + g + 8 * i;
        if (tq == 0 && r < B)
            out[r] = 1.0f / (1.0f + __expf(-(s + bo)));
    }
}

// ---------------------------------------------------------------------------
extern "C" void kernel_launch(void* const* d_in, const int* in_sizes, int n_in,
                              void* d_out, int out_size) {
    const int*   tokens = (const int*)  d_in[0];
    const float* emb    = (const float*)d_in[1];
    const float* Wx0    = (const float*)d_in[2];
    const float* Wh0    = (const float*)d_in[3];
    const float* b0     = (const float*)d_in[4];
    const float* Wx1    = (const float*)d_in[5];
    const float* Wh1    = (const float*)d_in[6];
    const float* b1     = (const float*)d_in[7];
    const float* Wout   = (const float*)d_in[8];
    const float* bout   = (const float*)d_in[9];
    float* out = (float*)d_out;

    int B = in_sizes[0] / SEQ;
    if (B > BMAX) B = BMAX;

    int prep_blocks = EMBW_BLOCKS + 1 + (B + 31) / 32;
    prep_kernel<<<prep_blocks, 256>>>(emb, Wx0, b0, Wh0, Wx1, Wh1, tokens, B);

    int nblocks = (B + 15) / 16;
    rnn_kernel<<<nblocks, 32>>>(b1, Wout, bout, out, B);
}